// round 8
// baseline (speedup 1.0000x reference)
#include <cuda_runtime.h>
#include <cuda_fp16.h>
#include <cstdint>
#include <math.h>

#define Tq 1536
#define CC 1536
#define T2 3071
#define NH 8
#define KH 64
#define VH 192
#define FF 192
#define HK 512
#define HV 1536
#define D1 3072

// ---------------- PTX helpers ----------------
__device__ __forceinline__ uint32_t smem_u32(const void* p) {
    uint32_t a;
    asm("{ .reg .u64 t; cvta.to.shared.u64 t, %1; cvt.u32.u64 %0, t; }" : "=r"(a) : "l"(p));
    return a;
}
#define CP_ASYNC16(dst, src) \
    asm volatile("cp.async.ca.shared.global [%0], [%1], 16;" :: "r"(dst), "l"(src) : "memory")
#define CP_COMMIT() asm volatile("cp.async.commit_group;" ::: "memory")
#define CP_WAIT(n)  asm volatile("cp.async.wait_group %0;" :: "n"(n) : "memory")
#define LDSM4(r0, r1, r2, r3, addr) \
    asm volatile("ldmatrix.sync.aligned.m8n8.x4.shared.b16 {%0,%1,%2,%3}, [%4];" \
        : "=r"(r0), "=r"(r1), "=r"(r2), "=r"(r3) : "r"(addr))

__device__ __forceinline__ void mma16(float* c, const uint32_t* a, const uint32_t* b) {
    asm volatile(
        "mma.sync.aligned.m16n8k16.row.col.f32.f16.f16.f32 "
        "{%0,%1,%2,%3}, {%4,%5,%6,%7}, {%8,%9}, {%0,%1,%2,%3};"
        : "+f"(c[0]), "+f"(c[1]), "+f"(c[2]), "+f"(c[3])
        : "r"(a[0]), "r"(a[1]), "r"(a[2]), "r"(a[3]), "r"(b[0]), "r"(b[1]));
}

// ---------------- scratch ----------------
__device__ __align__(128) float  g_logits[(size_t)NH * Tq * Tq];
__device__ __align__(128) float  g_y[Tq * CC];
__device__ __align__(128) __half h_xn[Tq * CC];
__device__ __align__(128) __half h_qw[Tq * HK];
__device__ __align__(128) __half h_qr[Tq * HK];
__device__ __align__(128) __half h_k[Tq * HK];
__device__ __align__(128) __half h_vT[HV * Tq];
__device__ __align__(128) __half h_pos[(T2 + 1) * FF];
__device__ __align__(128) __half h_rk[(T2 + 1) * HK];
__device__ __align__(128) __half h_probs[(size_t)NH * Tq * Tq];
__device__ __align__(128) __half h_o[Tq * HV];
__device__ __align__(128) __half h_yn[Tq * CC];
__device__ __align__(128) __half h_h1[Tq * D1];
__device__ __align__(128) __half h_WqkT[(HK * 2) * CC];
__device__ __align__(128) __half h_WvT[HV * CC];
__device__ __align__(128) __half h_WrT[HK * FF];
__device__ __align__(128) __half h_WoT[CC * HV];
__device__ __align__(128) __half h_W1T[D1 * CC];
__device__ __align__(128) __half h_W2T[CC * D1];

// ---------------- merged transpose: all 7 weights in one launch ----------------
__global__ void transpose_all(const float* __restrict__ Wq, const float* __restrict__ Wk,
                              const float* __restrict__ Wv, const float* __restrict__ Wr,
                              const float* __restrict__ Wo, const float* __restrict__ W1,
                              const float* __restrict__ W2) {
    int b = blockIdx.x;
    const float* in; __half* out; int Rr, Cc, bx, by; float scale = 1.f;
    if (b < 768)        { in = Wq; out = h_WqkT; Rr = CC; Cc = HK; scale = 0.125f; bx = b % 16; by = b / 16; }
    else if (b < 1536)  { b -= 768;  in = Wk; out = h_WqkT + (size_t)HK * CC; Rr = CC; Cc = HK; bx = b % 16; by = b / 16; }
    else if (b < 3840)  { b -= 1536; in = Wv; out = h_WvT; Rr = CC; Cc = HV; bx = b % 48; by = b / 48; }
    else if (b < 3936)  { b -= 3840; in = Wr; out = h_WrT; Rr = FF; Cc = HK; bx = b % 16; by = b / 16; }
    else if (b < 6240)  { b -= 3936; in = Wo; out = h_WoT; Rr = HV; Cc = CC; bx = b % 48; by = b / 48; }
    else if (b < 10848) { b -= 6240; in = W1; out = h_W1T; Rr = CC; Cc = D1; bx = b % 96; by = b / 96; }
    else                { b -= 10848; in = W2; out = h_W2T; Rr = D1; Cc = CC; bx = b % 48; by = b / 48; }
    __shared__ float t[32][33];
    int c0 = bx * 32, r0 = by * 32;
    int tx = threadIdx.x, ty = threadIdx.y;   // 32 x 8
#pragma unroll
    for (int i = 0; i < 4; i++)
        t[ty + 8 * i][tx] = in[(size_t)(r0 + ty + 8 * i) * Cc + c0 + tx];
    __syncthreads();
#pragma unroll
    for (int i = 0; i < 4; i++)
        out[(size_t)(c0 + ty + 8 * i) * Rr + r0 + tx] = __float2half_rn(t[tx][ty + 8 * i] * scale);
}

// ---------------- layernorm fp32 -> fp16 ----------------
__global__ void ln_kernel(const float* __restrict__ x, const float* __restrict__ g,
                          const float* __restrict__ b, __half* __restrict__ out) {
    int row = blockIdx.x;
    int tid = threadIdx.x;
    const float* xr = x + (size_t)row * CC;
    float v[6];
    float s = 0.f, s2 = 0.f;
#pragma unroll
    for (int e = 0; e < 6; e++) {
        float t = xr[tid + 256 * e];
        v[e] = t; s += t; s2 += t * t;
    }
    __shared__ float sh[16];
#pragma unroll
    for (int o = 16; o > 0; o >>= 1) {
        s  += __shfl_xor_sync(0xffffffffu, s, o);
        s2 += __shfl_xor_sync(0xffffffffu, s2, o);
    }
    int wid = tid >> 5, lane = tid & 31;
    if (lane == 0) { sh[wid] = s; sh[8 + wid] = s2; }
    __syncthreads();
    if (tid == 0) {
        float a = 0.f, c = 0.f;
        for (int i = 0; i < 8; i++) { a += sh[i]; c += sh[8 + i]; }
        sh[0] = a; sh[8] = c;
    }
    __syncthreads();
    float mu  = sh[0] * (1.f / CC);
    float var = sh[8] * (1.f / CC) - mu * mu;
    float rs  = rsqrtf(var + 1e-3f);
#pragma unroll
    for (int e = 0; e < 6; e++) {
        int c = tid + 256 * e;
        out[(size_t)row * CC + c] = __float2half_rn((v[e] - mu) * rs * g[c] + b[c]);
    }
}

// ---------------- fp16 mma NT GEMM (3-stage pipeline, XOR-swizzle addrs) ----------------
// MODE 0: fp32 out (+bias)(+resid)  MODE 1: fp16 out (+bias)(+relu)  MODE 3: fused QK
template<int MODE>
__global__ void __launch_bounds__(256) mma_gemm(
    const __half* __restrict__ A, int lda, long long strA,
    const __half* __restrict__ B, int ldb, long long strB,
    void* __restrict__ Cv, int ldc, long long strC,
    int M, int N, int Kd,
    const float* __restrict__ bias,
    const float* __restrict__ resid,
    int do_relu)
{
    const int row0 = blockIdx.y * 128, col0 = blockIdx.x * 128;
    extern __shared__ char smem_raw[];
    const uint32_t sbase = (smem_u32(smem_raw) + 127) & ~127u;
    const int tid = threadIdx.x;
    const int wid = tid >> 5, lane = tid & 31;
    const int wr = wid >> 2, wc = wid & 3;
    const long long z = blockIdx.z;
    A += z * strA; B += z * strB;

    // staging addresses (precomputed; per-stage base added later)
    uint32_t stOff[4];
    const __half* gA[4];
    const __half* gB[4];
#pragma unroll
    for (int it = 0; it < 4; it++) {
        int linear = tid + it * 256;
        int r = linear >> 3, g = linear & 7;
        stOff[it] = (uint32_t)(r * 128 + ((g ^ (r & 7)) << 4));
        int ra = row0 + r; if (ra >= M) ra = M - 1;
        int rb = col0 + r; if (rb >= N) rb = N - 1;
        gA[it] = A + (size_t)ra * lda + g * 8;
        gB[it] = B + (size_t)rb * ldb + g * 8;
    }
    auto stage = [&](int kc, int s) {
        uint32_t aS = sbase + s * 16384;
        uint32_t bS = sbase + 49152 + s * 16384;
        size_t koff = (size_t)kc * 64;
#pragma unroll
        for (int it = 0; it < 4; it++) {
            CP_ASYNC16(aS + stOff[it], gA[it] + koff);
            CP_ASYNC16(bS + stOff[it], gB[it] + koff);
        }
    };

    // fragment base offsets (XOR trick: addr = (base+off) ^ (gb<<4), bases 128-aligned)
    uint32_t offA[4], offB[2];
#pragma unroll
    for (int mi = 0; mi < 4; mi++) {
        int r = wr * 64 + mi * 16 + (lane & 15);
        offA[mi] = (uint32_t)(r * 128 + ((r & 7) << 4));
    }
#pragma unroll
    for (int nb = 0; nb < 2; nb++) {
        int n = wc * 32 + nb * 16 + (lane & 15);
        offB[nb] = (uint32_t)(n * 128 + ((n & 7) << 4));
    }
    const uint32_t laneSel = (uint32_t)(lane >> 4) << 4;

    float acc[16][4] = {};
    const int nc = Kd >> 6;
    stage(0, 0); CP_COMMIT();
    if (nc > 1) stage(1, 1);
    CP_COMMIT();
    for (int kc = 0; kc < nc; kc++) {
        int s = kc % 3;
        CP_WAIT(1);
        __syncthreads();
        if (kc + 2 < nc) stage(kc + 2, (kc + 2) % 3);
        CP_COMMIT();
        uint32_t aS = sbase + s * 16384;
        uint32_t bS = sbase + 49152 + s * 16384;
#pragma unroll
        for (int ks = 0; ks < 4; ks++) {
            uint32_t gsel = ((uint32_t)(ks * 2) << 4) ^ laneSel;
            uint32_t a[4][4], bfr[4][2];
#pragma unroll
            for (int mi = 0; mi < 4; mi++)
                LDSM4(a[mi][0], a[mi][1], a[mi][2], a[mi][3], (aS + offA[mi]) ^ gsel);
#pragma unroll
            for (int nb = 0; nb < 2; nb++) {
                uint32_t q0, q1, q2, q3;
                LDSM4(q0, q1, q2, q3, (bS + offB[nb]) ^ gsel);
                bfr[nb * 2][0] = q0;     bfr[nb * 2][1] = q2;
                bfr[nb * 2 + 1][0] = q1; bfr[nb * 2 + 1][1] = q3;
            }
#pragma unroll
            for (int mi = 0; mi < 4; mi++)
#pragma unroll
                for (int nj = 0; nj < 4; nj++)
                    mma16(acc[mi * 4 + nj], a[mi], bfr[nj]);
        }
        __syncthreads();
    }

#pragma unroll
    for (int mi = 0; mi < 4; mi++) {
#pragma unroll
        for (int hf = 0; hf < 2; hf++) {
            int r = row0 + wr * 64 + mi * 16 + (lane >> 2) + hf * 8;
            if (r >= M) continue;
#pragma unroll
            for (int nj = 0; nj < 4; nj++) {
                int cn = col0 + wc * 32 + nj * 8 + (lane & 3) * 2;
                float v0 = acc[mi * 4 + nj][hf * 2];
                float v1 = acc[mi * 4 + nj][hf * 2 + 1];
                if constexpr (MODE == 0) {
                    if (cn >= N) continue;
                    float* C = (float*)Cv + z * strC;
                    if (bias) { v0 += bias[cn]; v1 += bias[cn + 1]; }
                    if (resid) {
                        v0 += resid[(size_t)r * ldc + cn];
                        v1 += resid[(size_t)r * ldc + cn + 1];
                    }
                    *(float2*)(C + (size_t)r * ldc + cn) = make_float2(v0, v1);
                } else if constexpr (MODE == 1) {
                    if (cn >= N) continue;
                    __half* C = (__half*)Cv + z * strC;
                    if (bias) { v0 += bias[cn]; v1 += bias[cn + 1]; }
                    if (do_relu) { v0 = fmaxf(v0, 0.f); v1 = fmaxf(v1, 0.f); }
                    __half2 t;
                    t.x = __float2half_rn(v0); t.y = __float2half_rn(v1);
                    *(__half2*)(C + (size_t)r * ldc + cn) = t;
                } else {  // MODE 3: fused QK epilogue
                    if (cn < HK) {
                        __half2 tw, tr;
                        tw.x = __float2half_rn(v0 + bias[cn]);
                        tw.y = __float2half_rn(v1 + bias[cn + 1]);
                        tr.x = __float2half_rn(v0 + resid[cn]);
                        tr.y = __float2half_rn(v1 + resid[cn + 1]);
                        *(__half2*)(h_qw + (size_t)r * HK + cn) = tw;
                        *(__half2*)(h_qr + (size_t)r * HK + cn) = tr;
                    } else {
                        __half2 tk;
                        tk.x = __float2half_rn(v0); tk.y = __float2half_rn(v1);
                        *(__half2*)(h_k + (size_t)r * HK + cn - HK) = tk;
                    }
                }
            }
        }
    }
}

// ---------------- fused band logits: content + shifted rel, single write ----------------
#define LT_QW 0
#define LT_QR 16384
#define LT_K  32768
#define LT_RK 49152
#define LT_TILE 81920
#define LT_SMEM (81920 + 128 * 132 * 4 + 128)

__global__ void __launch_bounds__(256, 1) logits_kernel(float* __restrict__ logits) {
    extern __shared__ char smem_raw[];
    const uint32_t sbase = (smem_u32(smem_raw) + 127) & ~127u;
    float* sTile = (float*)(smem_raw + ((sbase - smem_u32(smem_raw)) + LT_TILE));
    const int h = blockIdx.z;
    const int q0 = blockIdx.y * 128, j0 = blockIdx.x * 128;
    const int tid = threadIdx.x;
    const int wid = tid >> 5, lane = tid & 31;
    const int wr = wid >> 2, wc = wid & 3;
    const int hoff = h * 64;
    const int base = (Tq - 1) + j0 - q0;   // m at (jl=0, ql=0)

    // stage qw, qr, k (128x64h) and rk window (256x64h)
#pragma unroll
    for (int it = 0; it < 4; it++) {
        int linear = tid + it * 256;
        int r = linear >> 3, g = linear & 7;
        uint32_t sw = (uint32_t)(r * 128 + ((g ^ (r & 7)) << 4));
        CP_ASYNC16(sbase + LT_QW + sw, h_qw + (size_t)(q0 + r) * HK + hoff + g * 8);
        CP_ASYNC16(sbase + LT_QR + sw, h_qr + (size_t)(q0 + r) * HK + hoff + g * 8);
        CP_ASYNC16(sbase + LT_K + sw, h_k + (size_t)(j0 + r) * HK + hoff + g * 8);
    }
#pragma unroll
    for (int it = 0; it < 8; it++) {
        int linear = tid + it * 256;
        int r = linear >> 3, g = linear & 7;
        int m = base - 128 + r;
        if (m < 0) m = 0;
        if (m > T2 - 1) m = T2 - 1;
        uint32_t sw = (uint32_t)(r * 128 + ((g ^ (r & 7)) << 4));
        CP_ASYNC16(sbase + LT_RK + sw, h_rk + (size_t)m * HK + hoff + g * 8);
    }
    CP_COMMIT();
    for (int i = tid; i < 128 * 132; i += 256) sTile[i] = 0.f;
    CP_WAIT(0);
    __syncthreads();

    // precomputed fragment offsets
    uint32_t offRow[4], offN[2], offRk2[4];
#pragma unroll
    for (int mi = 0; mi < 4; mi++) {
        int r = wr * 64 + mi * 16 + (lane & 15);
        offRow[mi] = (uint32_t)(r * 128 + ((r & 7) << 4));
    }
#pragma unroll
    for (int nb = 0; nb < 2; nb++) {
        int n = wc * 32 + nb * 16 + (lane & 15);
        offN[nb] = (uint32_t)(n * 128 + ((n & 7) << 4));
#pragma unroll
        for (int half = 0; half < 2; half++) {
            int nn = half * 128 + n;
            offRk2[half * 2 + nb] = (uint32_t)(nn * 128 + ((nn & 7) << 4));
        }
    }
    const uint32_t laneSel = (uint32_t)(lane >> 4) << 4;

    // rel band: two 128x128x64 GEMMs (qr @ rk-window^T), scatter into sTile
#pragma unroll
    for (int half = 0; half < 2; half++) {
        float acc[16][4] = {};
#pragma unroll
        for (int ks = 0; ks < 4; ks++) {
            uint32_t gsel = ((uint32_t)(ks * 2) << 4) ^ laneSel;
            uint32_t a[4][4], bfr[4][2];
#pragma unroll
            for (int mi = 0; mi < 4; mi++)
                LDSM4(a[mi][0], a[mi][1], a[mi][2], a[mi][3],
                      (sbase + LT_QR + offRow[mi]) ^ gsel);
#pragma unroll
            for (int nb = 0; nb < 2; nb++) {
                uint32_t p0, p1, p2, p3;
                LDSM4(p0, p1, p2, p3, (sbase + LT_RK + offRk2[half * 2 + nb]) ^ gsel);
                bfr[nb * 2][0] = p0;     bfr[nb * 2][1] = p2;
                bfr[nb * 2 + 1][0] = p1; bfr[nb * 2 + 1][1] = p3;
            }
#pragma unroll
            for (int mi = 0; mi < 4; mi++)
#pragma unroll
                for (int nj = 0; nj < 4; nj++)
                    mma16(acc[mi * 4 + nj], a[mi], bfr[nj]);
        }
        // scatter: jl = d - 128 + ql (race-free per row)
#pragma unroll
        for (int mi = 0; mi < 4; mi++)
#pragma unroll
            for (int hf = 0; hf < 2; hf++) {
                int ql = wr * 64 + mi * 16 + (lane >> 2) + hf * 8;
                float* trow = sTile + ql * 132;
#pragma unroll
                for (int nj = 0; nj < 4; nj++) {
                    int d = half * 128 + wc * 32 + nj * 8 + (lane & 3) * 2;
                    int jl = d - 128 + ql;
                    if (jl >= 0 && jl < 128) trow[jl] += acc[mi * 4 + nj][hf * 2];
                    if (jl + 1 >= 0 && jl + 1 < 128) trow[jl + 1] += acc[mi * 4 + nj][hf * 2 + 1];
                }
            }
    }

    // content GEMM (qw @ k^T)
    float acc[16][4] = {};
#pragma unroll
    for (int ks = 0; ks < 4; ks++) {
        uint32_t gsel = ((uint32_t)(ks * 2) << 4) ^ laneSel;
        uint32_t a[4][4], bfr[4][2];
#pragma unroll
        for (int mi = 0; mi < 4; mi++)
            LDSM4(a[mi][0], a[mi][1], a[mi][2], a[mi][3],
                  (sbase + LT_QW + offRow[mi]) ^ gsel);
#pragma unroll
        for (int nb = 0; nb < 2; nb++) {
            uint32_t p0, p1, p2, p3;
            LDSM4(p0, p1, p2, p3, (sbase + LT_K + offN[nb]) ^ gsel);
            bfr[nb * 2][0] = p0;     bfr[nb * 2][1] = p2;
            bfr[nb * 2 + 1][0] = p1; bfr[nb * 2 + 1][1] = p3;
        }
#pragma unroll
        for (int mi = 0; mi < 4; mi++)
#pragma unroll
            for (int nj = 0; nj < 4; nj++)
                mma16(acc[mi * 4 + nj], a[mi], bfr[nj]);
    }
    __syncthreads();   // scatters visible before epilogue reads sTile

    // epilogue: logits = content + band(rel), single write
#pragma unroll
    for (int mi = 0; mi < 4; mi++)
#pragma unroll
        for (int hf = 0; hf < 2; hf++) {
            int ql = wr * 64 + mi * 16 + (lane >> 2) + hf * 8;
            float* lrow = logits + ((size_t)h * Tq + q0 + ql) * Tq + j0;
            const float* trow = sTile + ql * 132;
#pragma unroll
            for (int nj = 0; nj < 4; nj++) {
                int cn = wc * 32 + nj * 8 + (lane & 3) * 2;
                float v0 = acc[mi * 4 + nj][hf * 2] + trow[cn];
                float v1 = acc[mi * 4 + nj][hf * 2 + 1] + trow[cn + 1];
                *(float2*)(lrow + cn) = make_float2(v0, v1);
            }
        }
}

// ---------------- positional features -> fp16 ----------------
__global__ void posfeat_kernel(__half* __restrict__ pos) {
    int warp = threadIdx.x >> 5, lane = threadIdx.x & 31;
    int p = blockIdx.x * 8 + warp;
    if (p >= T2) return;
    float d = (float)(p - (Tq - 1));
    float ap = fabsf(d);
    float sgn = (d > 0.f) ? 1.f : ((d < 0.f) ? -1.f : 0.f);
    double hi = 10.584962500721156;    // log2(1536)
    double exx = 3.0 + (hi - 3.0) * (double)lane / 31.0;
    float half_life = (float)exp2(exx);
    float coef = (float)(-(0.6931471805599453 / (double)half_life));
    float fexp = expf(ap * coef);
    float width = exp2f((float)(lane + 1)) - 1.f;
    float fcm = (width > ap) ? 1.f : 0.f;
    double mean = 48.0 + (1536.0 - 48.0) * (double)lane / 31.0;
    float conc = (float)((mean / 24.0) * (mean / 24.0));
    float rate = (float)(mean / 576.0);
    float log_unnorm = (conc - 1.f) * logf(ap) - rate * ap;
    float log_norm = lgammaf(conc) - conc * logf(rate);
    float prob = expf(log_unnorm - log_norm) + 1e-8f;
    float mx = prob;
#pragma unroll
    for (int o = 16; o > 0; o >>= 1) mx = fmaxf(mx, __shfl_xor_sync(0xffffffffu, mx, o));
    float fg = prob / mx;
    __half* row = pos + (size_t)p * FF;
    row[lane]       = __float2half_rn(fexp);
    row[32 + lane]  = __float2half_rn(fcm);
    row[64 + lane]  = __float2half_rn(fg);
    row[96 + lane]  = __float2half_rn(sgn * fexp);
    row[128 + lane] = __float2half_rn(sgn * fcm);
    row[160 + lane] = __float2half_rn(sgn * fg);
}

// ---------------- softmax: fp32 logits -> fp16 probs ----------------
__global__ void softmax_kernel(const float* __restrict__ logits, __half* __restrict__ probs) {
    int q = blockIdx.x, h = blockIdx.y;
    int tid = threadIdx.x;
    const float* row = logits + ((size_t)h * Tq + q) * Tq;
    __half* prow = probs + ((size_t)h * Tq + q) * Tq;
    float v[6];
    float mx = -1e30f;
#pragma unroll
    for (int e = 0; e < 6; e++) {
        v[e] = row[tid + 256 * e];
        mx = fmaxf(mx, v[e]);
    }
    __shared__ float sh[8];
#pragma unroll
    for (int o = 16; o > 0; o >>= 1) mx = fmaxf(mx, __shfl_xor_sync(0xffffffffu, mx, o));
    int wid = tid >> 5, lane = tid & 31;
    if (lane == 0) sh[wid] = mx;
    __syncthreads();
    if (tid == 0) { float m = sh[0]; for (int i = 1; i < 8; i++) m = fmaxf(m, sh[i]); sh[0] = m; }
    __syncthreads();
    mx = sh[0];
    __syncthreads();
    float s = 0.f;
#pragma unroll
    for (int e = 0; e < 6; e++) { v[e] = expf(v[e] - mx); s += v[e]; }
#pragma unroll
    for (int o = 16; o > 0; o >>= 1) s += __shfl_xor_sync(0xffffffffu, s, o);
    if (lane == 0) sh[wid] = s;
    __syncthreads();
    if (tid == 0) { float m = 0.f; for (int i = 0; i < 8; i++) m += sh[i]; sh[0] = m; }
    __syncthreads();
    float inv = 1.f / sh[0];
#pragma unroll
    for (int e = 0; e < 6; e++) prow[tid + 256 * e] = __float2half_rn(v[e] * inv);
}

// ---------------- host ----------------
#define GSMEM (98304 + 128)

extern "C" void kernel_launch(void* const* d_in, const int* in_sizes, int n_in,
                              void* d_out, int out_size) {
    (void)in_sizes; (void)n_in; (void)out_size;
    const float* x     = (const float*)d_in[0];
    const float* ln1_g = (const float*)d_in[1];
    const float* ln1_b = (const float*)d_in[2];
    const float* ln2_g = (const float*)d_in[3];
    const float* ln2_b = (const float*)d_in[4];
    const float* Wq    = (const float*)d_in[5];
    const float* Wk    = (const float*)d_in[6];
    const float* Wv    = (const float*)d_in[7];
    const float* Wr    = (const float*)d_in[8];
    const float* Wo    = (const float*)d_in[9];
    const float* bo    = (const float*)d_in[10];
    const float* rwb   = (const float*)d_in[11];
    const float* rrb   = (const float*)d_in[12];
    const float* W1    = (const float*)d_in[13];
    const float* b1    = (const float*)d_in[14];
    const float* W2    = (const float*)d_in[15];
    const float* b2    = (const float*)d_in[16];
    float* out = (float*)d_out;

    cudaFuncSetAttribute(mma_gemm<0>, cudaFuncAttributeMaxDynamicSharedMemorySize, GSMEM);
    cudaFuncSetAttribute(mma_gemm<1>, cudaFuncAttributeMaxDynamicSharedMemorySize, GSMEM);
    cudaFuncSetAttribute(mma_gemm<3>, cudaFuncAttributeMaxDynamicSharedMemorySize, GSMEM);
    cudaFuncSetAttribute(logits_kernel, cudaFuncAttributeMaxDynamicSharedMemorySize, LT_SMEM);

    float *logits, *y;
    __half *xn, *vT, *pos, *rk, *probs, *o, *yn, *h1;
    __half *WqkT, *WvT, *WrT, *WoT, *W1T, *W2T;
    cudaGetSymbolAddress((void**)&logits, g_logits);
    cudaGetSymbolAddress((void**)&y, g_y);
    cudaGetSymbolAddress((void**)&xn, h_xn);
    cudaGetSymbolAddress((void**)&vT, h_vT);
    cudaGetSymbolAddress((void**)&pos, h_pos);
    cudaGetSymbolAddress((void**)&rk, h_rk);
    cudaGetSymbolAddress((void**)&probs, h_probs);
    cudaGetSymbolAddress((void**)&o, h_o);
    cudaGetSymbolAddress((void**)&yn, h_yn);
    cudaGetSymbolAddress((void**)&h1, h_h1);
    cudaGetSymbolAddress((void**)&WqkT, h_WqkT);
    cudaGetSymbolAddress((void**)&WvT, h_WvT);
    cudaGetSymbolAddress((void**)&WrT, h_WrT);
    cudaGetSymbolAddress((void**)&WoT, h_WoT);
    cudaGetSymbolAddress((void**)&W1T, h_W1T);
    cudaGetSymbolAddress((void**)&W2T, h_W2T);

    transpose_all<<<15456, dim3(32, 8)>>>(Wq, Wk, Wv, Wr, Wo, W1, W2);
    ln_kernel<<<Tq, 256>>>(x, ln1_g, ln1_b, xn);
    // fused QK: writes qw, qr, k
    mma_gemm<3><<<dim3(8, 12), 256, GSMEM>>>(
        xn, CC, 0, WqkT, CC, 0, nullptr, 0, 0, Tq, HK * 2, CC, rwb, rrb, 0);
    // vT = WvT @ xn^T
    mma_gemm<1><<<dim3(12, 12), 256, GSMEM>>>(
        WvT, CC, 0, xn, CC, 0, vT, Tq, 0, HV, Tq, CC, nullptr, nullptr, 0);
    posfeat_kernel<<<(T2 + 7) / 8, 256>>>(pos);
    mma_gemm<1><<<dim3(4, 24), 256, GSMEM>>>(
        pos, FF, 0, WrT, FF, 0, rk, HK, 0, T2, HK, FF, nullptr, nullptr, 0);
    // fused band logits
    logits_kernel<<<dim3(12, 12, NH), 256, LT_SMEM>>>(logits);
    softmax_kernel<<<dim3(Tq, NH), 256>>>(logits, probs);
    // o = probs @ v
    mma_gemm<1><<<dim3(2, 12, NH), 256, GSMEM>>>(
        probs, Tq, (long long)Tq * Tq, vT, Tq, (long long)VH * Tq,
        o, HV, VH, Tq, VH, Tq, nullptr, nullptr, 0);
    // y = x + o @ Wo + bo
    mma_gemm<0><<<dim3(12, 12), 256, GSMEM>>>(
        o, HV, 0, WoT, HV, 0, y, CC, 0, Tq, CC, HV, bo, x, 0);
    ln_kernel<<<Tq, 256>>>(y, ln2_g, ln2_b, yn);
    mma_gemm<1><<<dim3(24, 12), 256, GSMEM>>>(
        yn, CC, 0, W1T, CC, 0, h1, D1, 0, Tq, D1, CC, b1, nullptr, 1);
    mma_gemm<0><<<dim3(12, 12), 256, GSMEM>>>(
        h1, D1, 0, W2T, D1, 0, out, CC, 0, Tq, CC, D1, b2, y, 0);
}